// round 1
// baseline (speedup 1.0000x reference)
#include <cuda_runtime.h>
#include <cstdint>

// ---------------------------------------------------------------------------
// WindowAttention (Swin-style), fp32 baseline.
// B=8192 windows, N=64 tokens, DIM=256, HEADS=8, HEAD_DIM=32, nW=4096 masks.
//   qkv = x @ [wq;wkv]^T + [bq;bkv]          (GEMM1: 524288 x 768 x 256)
//   s   = scale*q k^T + rel_bias + mask ; softmax ; o = s v
//   out = o @ wp^T + bp                      (GEMM2: 524288 x 256 x 256)
// ---------------------------------------------------------------------------

#define NWIN    8192
#define NTOK    64
#define DIM     256
#define HEADS   8
#define HDIM    32
#define NMASK   4096
#define SCALE   0.17677669529663687f   // 32^-0.5
#define QKVC    768
#define TBL_N   (15 * 15)              // (2*8-1)^2 = 225

// Scratch (static device arrays: allocation-free per harness rules)
__device__ float g_qkv[(size_t)NWIN * NTOK * QKVC];  // 1.61 GB
__device__ float g_o  [(size_t)NWIN * NTOK * DIM];   // 512 MB

// ---------------------------------------------------------------------------
// Tiled SGEMM:  C[M,N] = A[M,K] * B[N,K]^T + bias
// B rows come from B0 (row < nsplit) or B1 (row - nsplit); bias likewise.
// BM=BN=128, BK=16, 256 threads, 8x8 register micro-tile.
// Requires M%128==0, N%128==0, K%16==0 (true for all our shapes).
// ---------------------------------------------------------------------------
#define BM 128
#define BN 128
#define BK 16

__global__ __launch_bounds__(256)
void sgemm_nt(const float* __restrict__ A,
              const float* __restrict__ B0, const float* __restrict__ B1,
              int nsplit,
              const float* __restrict__ bias0, const float* __restrict__ bias1,
              float* __restrict__ C, int M, int N, int K)
{
    __shared__ __align__(16) float As[BK][BM + 4];
    __shared__ __align__(16) float Bs[BK][BN + 4];

    const int tid = threadIdx.x;
    const int bm  = blockIdx.y;
    const int bn  = blockIdx.x;

    // loader lanes: each thread loads 2x float4 from A and 2x float4 from B
    const int lr = tid >> 2;          // 0..63
    const int lk = (tid & 3) << 2;    // 0,4,8,12

    const float* Ar0 = A + (size_t)(bm * BM + lr) * K + lk;
    const float* Ar1 = Ar0 + (size_t)64 * K;

    const int n0g = bn * BN + lr;
    const int n1g = n0g + 64;
    const float* Br0 = (n0g < nsplit) ? (B0 + (size_t)n0g * K + lk)
                                      : (B1 + (size_t)(n0g - nsplit) * K + lk);
    const float* Br1 = (n1g < nsplit) ? (B0 + (size_t)n1g * K + lk)
                                      : (B1 + (size_t)(n1g - nsplit) * K + lk);

    const int ty = tid >> 4;          // 0..15 (row group)
    const int tx = tid & 15;          // 0..15 (col group)

    float acc[8][8];
#pragma unroll
    for (int i = 0; i < 8; i++)
#pragma unroll
        for (int j = 0; j < 8; j++) acc[i][j] = 0.f;

    for (int k0 = 0; k0 < K; k0 += BK) {
        float4 a0 = *(const float4*)(Ar0 + k0);
        float4 a1 = *(const float4*)(Ar1 + k0);
        float4 b0 = *(const float4*)(Br0 + k0);
        float4 b1 = *(const float4*)(Br1 + k0);

        __syncthreads();   // previous tile fully consumed
        As[lk + 0][lr] = a0.x; As[lk + 1][lr] = a0.y;
        As[lk + 2][lr] = a0.z; As[lk + 3][lr] = a0.w;
        As[lk + 0][lr + 64] = a1.x; As[lk + 1][lr + 64] = a1.y;
        As[lk + 2][lr + 64] = a1.z; As[lk + 3][lr + 64] = a1.w;
        Bs[lk + 0][lr] = b0.x; Bs[lk + 1][lr] = b0.y;
        Bs[lk + 2][lr] = b0.z; Bs[lk + 3][lr] = b0.w;
        Bs[lk + 0][lr + 64] = b1.x; Bs[lk + 1][lr + 64] = b1.y;
        Bs[lk + 2][lr + 64] = b1.z; Bs[lk + 3][lr + 64] = b1.w;
        __syncthreads();

#pragma unroll
        for (int kk = 0; kk < BK; kk++) {
            float a[8], b[8];
            float4 t;
            t = *(const float4*)&As[kk][ty * 8];     a[0]=t.x; a[1]=t.y; a[2]=t.z; a[3]=t.w;
            t = *(const float4*)&As[kk][ty * 8 + 4]; a[4]=t.x; a[5]=t.y; a[6]=t.z; a[7]=t.w;
            t = *(const float4*)&Bs[kk][tx * 8];     b[0]=t.x; b[1]=t.y; b[2]=t.z; b[3]=t.w;
            t = *(const float4*)&Bs[kk][tx * 8 + 4]; b[4]=t.x; b[5]=t.y; b[6]=t.z; b[7]=t.w;
#pragma unroll
            for (int i = 0; i < 8; i++)
#pragma unroll
                for (int j = 0; j < 8; j++)
                    acc[i][j] += a[i] * b[j];
        }
    }

    // epilogue: add bias, store
    const int crow = bm * BM + ty * 8;
    const int ccol = bn * BN + tx * 8;
    float bv[8];
#pragma unroll
    for (int j = 0; j < 8; j++) {
        int col = ccol + j;
        bv[j] = (col < nsplit) ? bias0[col] : bias1[col - nsplit];
    }
#pragma unroll
    for (int i = 0; i < 8; i++) {
        float4 r0, r1;
        r0.x = acc[i][0] + bv[0]; r0.y = acc[i][1] + bv[1];
        r0.z = acc[i][2] + bv[2]; r0.w = acc[i][3] + bv[3];
        r1.x = acc[i][4] + bv[4]; r1.y = acc[i][5] + bv[5];
        r1.z = acc[i][6] + bv[6]; r1.w = acc[i][7] + bv[7];
        float* cp = C + (size_t)(crow + i) * N + ccol;
        *(float4*)(cp)     = r0;
        *(float4*)(cp + 4) = r1;
    }
}

// ---------------------------------------------------------------------------
// Attention: 1 CTA per window (8192 CTAs, 256 threads).
// Per head: stage q/k/v [64x32] in smem, s = scale*q k^T + bias + mask,
// warp-level softmax, o = p v written to g_o.
// ---------------------------------------------------------------------------
__global__ __launch_bounds__(256)
void attn_kernel(const float* __restrict__ qkv,        // [B*64, 768]
                 const float* __restrict__ mask,       // [4096, 64, 64]
                 const float* __restrict__ bias_table, // [225, 8]
                 const int*   __restrict__ rel_idx,    // [64, 64]
                 float* __restrict__ o)                // [B*64, 256]
{
    __shared__ float qs[64][33];
    __shared__ float ks[64][33];
    __shared__ __align__(16) float vs[64][32];
    __shared__ float ss[64][65];
    __shared__ float tbl[TBL_N * HEADS];

    const int b   = blockIdx.x;
    const int tid = threadIdx.x;

    for (int i = tid; i < TBL_N * HEADS; i += 256)
        tbl[i] = bias_table[i];

    const float* mrow = mask + (size_t)(b & (NMASK - 1)) * (NTOK * NTOK);
    const float* base = qkv + (size_t)b * NTOK * QKVC;

    // loader lanes
    const int r  = tid >> 2;          // 0..63
    const int c8 = (tid & 3) * 8;     // 0,8,16,24

    // s-compute lanes: 4x4 tile
    const int n0 = (tid >> 4) * 4;
    const int m0 = (tid & 15) * 4;
    // AV lanes: 4x2 tile
    const int d0 = (tid & 15) * 2;

    const int wid  = tid >> 5;
    const int lane = tid & 31;

    for (int h = 0; h < HEADS; h++) {
        const float* qp = base + (size_t)r * QKVC + h * HDIM + c8;
        float4 q0 = *(const float4*)(qp);
        float4 q1 = *(const float4*)(qp + 4);
        float4 k0 = *(const float4*)(qp + 256);
        float4 k1 = *(const float4*)(qp + 260);
        float4 v0 = *(const float4*)(qp + 512);
        float4 v1 = *(const float4*)(qp + 516);

        __syncthreads();   // previous head done with vs/ss (and first-head tbl visible)
        qs[r][c8+0]=q0.x; qs[r][c8+1]=q0.y; qs[r][c8+2]=q0.z; qs[r][c8+3]=q0.w;
        qs[r][c8+4]=q1.x; qs[r][c8+5]=q1.y; qs[r][c8+6]=q1.z; qs[r][c8+7]=q1.w;
        ks[r][c8+0]=k0.x; ks[r][c8+1]=k0.y; ks[r][c8+2]=k0.z; ks[r][c8+3]=k0.w;
        ks[r][c8+4]=k1.x; ks[r][c8+5]=k1.y; ks[r][c8+6]=k1.z; ks[r][c8+7]=k1.w;
        vs[r][c8+0]=v0.x; vs[r][c8+1]=v0.y; vs[r][c8+2]=v0.z; vs[r][c8+3]=v0.w;
        vs[r][c8+4]=v1.x; vs[r][c8+5]=v1.y; vs[r][c8+6]=v1.z; vs[r][c8+7]=v1.w;
        __syncthreads();

        // s = q k^T (4x4 register tile per thread)
        float sacc[4][4];
#pragma unroll
        for (int i = 0; i < 4; i++)
#pragma unroll
            for (int j = 0; j < 4; j++) sacc[i][j] = 0.f;

#pragma unroll
        for (int d = 0; d < HDIM; d++) {
            float qv[4], kv[4];
#pragma unroll
            for (int i = 0; i < 4; i++) qv[i] = qs[n0 + i][d];
#pragma unroll
            for (int j = 0; j < 4; j++) kv[j] = ks[m0 + j][d];
#pragma unroll
            for (int i = 0; i < 4; i++)
#pragma unroll
                for (int j = 0; j < 4; j++)
                    sacc[i][j] += qv[i] * kv[j];
        }
#pragma unroll
        for (int i = 0; i < 4; i++) {
#pragma unroll
            for (int j = 0; j < 4; j++) {
                const int n = n0 + i, m = m0 + j;
                const int idx = rel_idx[n * NTOK + m];
                ss[n][m] = sacc[i][j] * SCALE + tbl[idx * HEADS + h]
                         + mrow[n * NTOK + m];
            }
        }
        __syncthreads();

        // softmax: each warp handles rows wid, wid+8, ...
        for (int row = wid; row < NTOK; row += 8) {
            float v0e = ss[row][lane];
            float v1e = ss[row][lane + 32];
            float mx = fmaxf(v0e, v1e);
#pragma unroll
            for (int off = 16; off > 0; off >>= 1)
                mx = fmaxf(mx, __shfl_xor_sync(0xffffffffu, mx, off));
            float e0 = __expf(v0e - mx);
            float e1 = __expf(v1e - mx);
            float sm = e0 + e1;
#pragma unroll
            for (int off = 16; off > 0; off >>= 1)
                sm += __shfl_xor_sync(0xffffffffu, sm, off);
            float inv = 1.f / sm;
            ss[row][lane]      = e0 * inv;
            ss[row][lane + 32] = e1 * inv;
        }
        __syncthreads();

        // o = p v (4 rows x 2 cols per thread)
        float oacc[4][2];
#pragma unroll
        for (int i = 0; i < 4; i++) { oacc[i][0] = 0.f; oacc[i][1] = 0.f; }

#pragma unroll 8
        for (int m = 0; m < NTOK; m++) {
            float2 vv = *(const float2*)&vs[m][d0];
#pragma unroll
            for (int i = 0; i < 4; i++) {
                float p = ss[n0 + i][m];
                oacc[i][0] += p * vv.x;
                oacc[i][1] += p * vv.y;
            }
        }
#pragma unroll
        for (int i = 0; i < 4; i++) {
            float2 ov; ov.x = oacc[i][0]; ov.y = oacc[i][1];
            *(float2*)(o + ((size_t)b * NTOK + n0 + i) * DIM + h * HDIM + d0) = ov;
        }
    }
}

// ---------------------------------------------------------------------------
extern "C" void kernel_launch(void* const* d_in, const int* in_sizes, int n_in,
                              void* d_out, int out_size)
{
    const float* x          = (const float*)d_in[0];
    const float* mask       = (const float*)d_in[1];
    const float* wq         = (const float*)d_in[2];
    const float* bq         = (const float*)d_in[3];
    const float* wkv        = (const float*)d_in[4];
    const float* bkv        = (const float*)d_in[5];
    const float* wp         = (const float*)d_in[6];
    const float* bp         = (const float*)d_in[7];
    const float* bias_table = (const float*)d_in[8];
    const int*   rel_idx    = (const int*)d_in[9];
    float* out = (float*)d_out;

    float* qkv_ptr = nullptr;
    float* o_ptr   = nullptr;
    cudaGetSymbolAddress((void**)&qkv_ptr, g_qkv);
    cudaGetSymbolAddress((void**)&o_ptr,   g_o);

    const int M = NWIN * NTOK;   // 524288

    // 1) QKV projection: [M,768] = x[M,256] @ [wq;wkv]^T + [bq;bkv]
    sgemm_nt<<<dim3(QKVC / BN, M / BM), 256>>>(
        x, wq, wkv, /*nsplit=*/DIM, bq, bkv, qkv_ptr, M, QKVC, DIM);

    // 2) windowed attention
    attn_kernel<<<NWIN, 256>>>(qkv_ptr, mask, bias_table, rel_idx, o_ptr);

    // 3) output projection: out[M,256] = o[M,256] @ wp^T + bp
    sgemm_nt<<<dim3(DIM / BN, M / BM), 256>>>(
        o_ptr, wp, wp, /*nsplit=*/1 << 30, bp, bp, out, M, DIM, DIM);
}

// round 3
// speedup vs baseline: 2.2673x; 2.2673x over previous
#include <cuda_runtime.h>
#include <cuda_fp16.h>
#include <cstdint>

// ---------------------------------------------------------------------------
// WindowAttention (Swin-style), Round 3.
// tcgen05 unavailable (harness lowers via compute_103, no 'a' features).
// Projection GEMMs -> fp16 mma.sync (HMMA) + ldmatrix + cp.async.
// B=8192 windows, N=64 tokens, DIM=256, HEADS=8, HEAD_DIM=32, nW=4096 masks.
// ---------------------------------------------------------------------------

#define NWIN    8192
#define NTOK    64
#define DIM     256
#define HEADS   8
#define HDIM    32
#define NMASK   4096
#define SCALE   0.17677669529663687f   // 32^-0.5
#define QKVC    768
#define TBL_N   (15 * 15)

// Scratch (static device arrays: allocation-free per harness rules)
__device__ __half g_xh  [(size_t)NWIN * NTOK * DIM];   // 268 MB
__device__ __half g_qkvh[(size_t)NWIN * NTOK * QKVC];  // 805 MB
__device__ __half g_oh  [(size_t)NWIN * NTOK * DIM];   // 268 MB
__device__ __half g_wh  [QKVC * DIM];                  // [wq;wkv] fp16
__device__ __half g_wph [DIM * DIM];                   // wp fp16

// ======================= PTX helpers (base ISA only) =======================
#define CP_ASYNC16(dst, src) \
    asm volatile("cp.async.ca.shared.global [%0], [%1], 16;" \
                 :: "r"(dst), "l"(src) : "memory")
#define CP_COMMIT() asm volatile("cp.async.commit_group;" ::: "memory")
#define CP_WAIT1()  asm volatile("cp.async.wait_group 1;" ::: "memory")
#define CP_WAIT0()  asm volatile("cp.async.wait_group 0;" ::: "memory")

__device__ __forceinline__ void ldm_x4(uint32_t* r, uint32_t addr) {
    asm volatile("ldmatrix.sync.aligned.m8n8.x4.shared.b16 {%0,%1,%2,%3}, [%4];"
                 : "=r"(r[0]), "=r"(r[1]), "=r"(r[2]), "=r"(r[3]) : "r"(addr));
}
__device__ __forceinline__ void ldm_x2(uint32_t* r, uint32_t addr) {
    asm volatile("ldmatrix.sync.aligned.m8n8.x2.shared.b16 {%0,%1}, [%2];"
                 : "=r"(r[0]), "=r"(r[1]) : "r"(addr));
}
__device__ __forceinline__ void mma16816(float* c, const uint32_t* a, const uint32_t* b) {
    asm volatile(
        "mma.sync.aligned.m16n8k16.row.col.f32.f16.f16.f32 "
        "{%0,%1,%2,%3}, {%4,%5,%6,%7}, {%8,%9}, {%0,%1,%2,%3};"
        : "+f"(c[0]), "+f"(c[1]), "+f"(c[2]), "+f"(c[3])
        : "r"(a[0]), "r"(a[1]), "r"(a[2]), "r"(a[3]), "r"(b[0]), "r"(b[1]));
}

// ---------------------------------------------------------------------------
// fp32 -> fp16 converter (n must be a multiple of 8; grids sized exactly)
// ---------------------------------------------------------------------------
__global__ __launch_bounds__(256)
void cvt_f32_f16(const float* __restrict__ in, __half* __restrict__ out, int n)
{
    int i = (blockIdx.x * 256 + threadIdx.x) * 8;
    if (i + 8 <= n) {
        float4 a = *(const float4*)(in + i);
        float4 b = *(const float4*)(in + i + 4);
        __half2 h[4];
        h[0] = __floats2half2_rn(a.x, a.y);
        h[1] = __floats2half2_rn(a.z, a.w);
        h[2] = __floats2half2_rn(b.x, b.y);
        h[3] = __floats2half2_rn(b.z, b.w);
        *(uint4*)(out + i) = *(const uint4*)h;
    }
}

// ---------------------------------------------------------------------------
// fp16 tensor-core GEMM:  C[M,N] = A[M,K](f16) * B[N,K](f16)^T + bias(f32)
// Tile 128x128x32, 256 threads = 8 warps (2 m x 4 n), warp tile 64x32.
// cp.async double-buffered smem, padded rows (40 halves) for conflict-free
// ldmatrix. A: ldmatrix.x4 (row-major). B ([n][k] row-major == col-major kxn
// for row.col mma): ldmatrix.x2 non-trans.
// bias col < nsplit -> bias0[col], else bias1[col-nsplit].
// ---------------------------------------------------------------------------
#define LDH   40                         // halves per smem row (32 + 8 pad)
#define BUFB  (128 * LDH * 2)            // bytes per (matrix) buffer

template <bool HALF_OUT>
__global__ __launch_bounds__(256, 2)
void gemm_f16(const __half* __restrict__ A, const __half* __restrict__ B,
              const float* __restrict__ bias0, const float* __restrict__ bias1,
              int nsplit, void* __restrict__ Cv, int M, int N_, int K)
{
    __shared__ __align__(16) __half sA[2][128 * LDH];
    __shared__ __align__(16) __half sB[2][128 * LDH];

    const int tid   = threadIdx.x;
    const int bm    = blockIdx.y;
    const int bn    = blockIdx.x;
    const int wid   = tid >> 5;
    const int lane  = tid & 31;
    const int warpM = wid & 1;           // 0..1  (64-row slab)
    const int warpN = wid >> 1;          // 0..3  (32-col slab)

    // ---- loader mapping: thread t -> row t>>1, 16 halves at (t&1)*16
    const int lrow = tid >> 1;
    const int lk   = (tid & 1) << 4;
    const __half* Ag = A + (size_t)(bm * 128 + lrow) * K + lk;
    const __half* Bg = B + (size_t)(bn * 128 + lrow) * K + lk;

    const uint32_t sA0 = (uint32_t)__cvta_generic_to_shared(&sA[0][0]);
    const uint32_t sB0 = (uint32_t)__cvta_generic_to_shared(&sB[0][0]);
    const uint32_t ldst = (uint32_t)(lrow * LDH + lk) * 2;

    // ---- mma smem offsets (bytes, buffer-relative)
    const uint32_t aoff = (uint32_t)(((warpM * 64 + (lane & 15)) * LDH
                                      + (lane >> 4) * 8) * 2);
    const uint32_t boff = (uint32_t)(((warpN * 32 + (lane & 7)) * LDH
                                      + ((lane >> 3) & 1) * 8) * 2);

    float acc[4][4][4];
#pragma unroll
    for (int mt = 0; mt < 4; mt++)
#pragma unroll
        for (int nt = 0; nt < 4; nt++)
#pragma unroll
            for (int k = 0; k < 4; k++) acc[mt][nt][k] = 0.f;

    const int nchunk = K >> 5;           // 8 for K=256

    // prologue: chunk 0 -> buffer 0
    CP_ASYNC16(sA0 + ldst,      Ag);
    CP_ASYNC16(sA0 + ldst + 16, Ag + 8);
    CP_ASYNC16(sB0 + ldst,      Bg);
    CP_ASYNC16(sB0 + ldst + 16, Bg + 8);
    CP_COMMIT();

    for (int c = 0; c < nchunk; c++) {
        if (c + 1 < nchunk) {
            const uint32_t bsel = (uint32_t)((c + 1) & 1) * BUFB;
            const __half* a = Ag + (c + 1) * 32;
            const __half* b = Bg + (c + 1) * 32;
            CP_ASYNC16(sA0 + bsel + ldst,      a);
            CP_ASYNC16(sA0 + bsel + ldst + 16, a + 8);
            CP_ASYNC16(sB0 + bsel + ldst,      b);
            CP_ASYNC16(sB0 + bsel + ldst + 16, b + 8);
            CP_COMMIT();
            CP_WAIT1();
        } else {
            CP_WAIT0();
        }
        __syncthreads();

        const uint32_t bufo = (uint32_t)(c & 1) * BUFB;
#pragma unroll
        for (int ks = 0; ks < 2; ks++) {
            uint32_t af[4][4], bf[4][2];
#pragma unroll
            for (int mt = 0; mt < 4; mt++)
                ldm_x4(af[mt], sA0 + bufo + aoff + (uint32_t)((mt * 16 * LDH + ks * 16) * 2));
#pragma unroll
            for (int nt = 0; nt < 4; nt++)
                ldm_x2(bf[nt], sB0 + bufo + boff + (uint32_t)((nt * 8 * LDH + ks * 16) * 2));
#pragma unroll
            for (int mt = 0; mt < 4; mt++)
#pragma unroll
                for (int nt = 0; nt < 4; nt++)
                    mma16816(acc[mt][nt], af[mt], bf[nt]);
        }
        __syncthreads();
    }

    // ---- epilogue
    const int gr0 = bm * 128 + warpM * 64 + (lane >> 2);
    const int gc0 = bn * 128 + warpN * 32 + (lane & 3) * 2;
#pragma unroll
    for (int mt = 0; mt < 4; mt++) {
#pragma unroll
        for (int nt = 0; nt < 4; nt++) {
            const int col = gc0 + nt * 8;
            const float b0v = (col     < nsplit) ? bias0[col]     : bias1[col - nsplit];
            const float b1v = (col + 1 < nsplit) ? bias0[col + 1] : bias1[col + 1 - nsplit];
            const int r0 = gr0 + mt * 16;
            if (HALF_OUT) {
                __half* C = (__half*)Cv;
                *(__half2*)(C + (size_t)r0 * N_ + col) =
                    __floats2half2_rn(acc[mt][nt][0] + b0v, acc[mt][nt][1] + b1v);
                *(__half2*)(C + (size_t)(r0 + 8) * N_ + col) =
                    __floats2half2_rn(acc[mt][nt][2] + b0v, acc[mt][nt][3] + b1v);
            } else {
                float* C = (float*)Cv;
                float2 v0; v0.x = acc[mt][nt][0] + b0v; v0.y = acc[mt][nt][1] + b1v;
                float2 v1; v1.x = acc[mt][nt][2] + b0v; v1.y = acc[mt][nt][3] + b1v;
                *(float2*)(C + (size_t)r0 * N_ + col)       = v0;
                *(float2*)(C + (size_t)(r0 + 8) * N_ + col) = v1;
            }
        }
    }
}

// ---------------------------------------------------------------------------
// Attention: 1 CTA per window (8192 CTAs, 256 threads). fp16 qkv in, fp16 o out.
// ---------------------------------------------------------------------------
__device__ __forceinline__ void unpack8(uint4 u, float* dst) {
    const __half2* h = (const __half2*)&u;
    float2 t0 = __half22float2(h[0]);
    float2 t1 = __half22float2(h[1]);
    float2 t2 = __half22float2(h[2]);
    float2 t3 = __half22float2(h[3]);
    dst[0] = t0.x; dst[1] = t0.y; dst[2] = t1.x; dst[3] = t1.y;
    dst[4] = t2.x; dst[5] = t2.y; dst[6] = t3.x; dst[7] = t3.y;
}

__global__ __launch_bounds__(256)
void attn_kernel(const __half* __restrict__ qkv,      // [B*64, 768] f16
                 const float* __restrict__ mask,       // [4096, 64, 64]
                 const float* __restrict__ bias_table, // [225, 8]
                 const int*   __restrict__ rel_idx,    // [64, 64]
                 __half* __restrict__ o)               // [B*64, 256] f16
{
    __shared__ float qs[64][33];
    __shared__ float ks[64][33];
    __shared__ float vs[64][33];
    __shared__ float ss[64][65];
    __shared__ float tbl[TBL_N * HEADS];

    const int b   = blockIdx.x;
    const int tid = threadIdx.x;

    for (int i = tid; i < TBL_N * HEADS; i += 256)
        tbl[i] = bias_table[i];

    const float* mrow = mask + (size_t)(b & (NMASK - 1)) * (NTOK * NTOK);
    const __half* base = qkv + (size_t)b * NTOK * QKVC;

    const int r  = tid >> 2;
    const int c8 = (tid & 3) * 8;

    const int n0 = (tid >> 4) * 4;
    const int m0 = (tid & 15) * 4;
    const int d0 = (tid & 15) * 2;

    const int wid  = tid >> 5;
    const int lane = tid & 31;

    for (int h = 0; h < HEADS; h++) {
        const __half* qp = base + (size_t)r * QKVC + h * HDIM + c8;
        uint4 qu = *(const uint4*)(qp);
        uint4 ku = *(const uint4*)(qp + 256);
        uint4 vu = *(const uint4*)(qp + 512);

        __syncthreads();   // previous head done with smem
        unpack8(qu, &qs[r][c8]);
        unpack8(ku, &ks[r][c8]);
        unpack8(vu, &vs[r][c8]);
        __syncthreads();

        // s = q k^T (4x4 register tile per thread)
        float sacc[4][4];
#pragma unroll
        for (int i = 0; i < 4; i++)
#pragma unroll
            for (int j = 0; j < 4; j++) sacc[i][j] = 0.f;

#pragma unroll
        for (int d = 0; d < HDIM; d++) {
            float qv[4], kv[4];
#pragma unroll
            for (int i = 0; i < 4; i++) qv[i] = qs[n0 + i][d];
#pragma unroll
            for (int j = 0; j < 4; j++) kv[j] = ks[m0 + j][d];
#pragma unroll
            for (int i = 0; i < 4; i++)
#pragma unroll
                for (int j = 0; j < 4; j++)
                    sacc[i][j] += qv[i] * kv[j];
        }
#pragma unroll
        for (int i = 0; i < 4; i++) {
#pragma unroll
            for (int j = 0; j < 4; j++) {
                const int n = n0 + i, m = m0 + j;
                const int idx = rel_idx[n * NTOK + m];
                ss[n][m] = sacc[i][j] * SCALE + tbl[idx * HEADS + h]
                         + mrow[n * NTOK + m];
            }
        }
        __syncthreads();

        // softmax: warp per row-group
        for (int row = wid; row < NTOK; row += 8) {
            float v0e = ss[row][lane];
            float v1e = ss[row][lane + 32];
            float mx = fmaxf(v0e, v1e);
#pragma unroll
            for (int off = 16; off > 0; off >>= 1)
                mx = fmaxf(mx, __shfl_xor_sync(0xffffffffu, mx, off));
            float e0 = __expf(v0e - mx);
            float e1 = __expf(v1e - mx);
            float sm = e0 + e1;
#pragma unroll
            for (int off = 16; off > 0; off >>= 1)
                sm += __shfl_xor_sync(0xffffffffu, sm, off);
            float inv = 1.f / sm;
            ss[row][lane]      = e0 * inv;
            ss[row][lane + 32] = e1 * inv;
        }
        __syncthreads();

        // o = p v (4 rows x 2 cols per thread)
        float oacc[4][2];
#pragma unroll
        for (int i = 0; i < 4; i++) { oacc[i][0] = 0.f; oacc[i][1] = 0.f; }

#pragma unroll 8
        for (int m = 0; m < NTOK; m++) {
            float vv0 = vs[m][d0];
            float vv1 = vs[m][d0 + 1];
#pragma unroll
            for (int i = 0; i < 4; i++) {
                float p = ss[n0 + i][m];
                oacc[i][0] += p * vv0;
                oacc[i][1] += p * vv1;
            }
        }
#pragma unroll
        for (int i = 0; i < 4; i++) {
            *(__half2*)(o + ((size_t)b * NTOK + n0 + i) * DIM + h * HDIM + d0) =
                __floats2half2_rn(oacc[i][0], oacc[i][1]);
        }
    }
}

// ---------------------------------------------------------------------------
extern "C" void kernel_launch(void* const* d_in, const int* in_sizes, int n_in,
                              void* d_out, int out_size)
{
    const float* x          = (const float*)d_in[0];
    const float* mask       = (const float*)d_in[1];
    const float* wq         = (const float*)d_in[2];
    const float* bq         = (const float*)d_in[3];
    const float* wkv        = (const float*)d_in[4];
    const float* bkv        = (const float*)d_in[5];
    const float* wp         = (const float*)d_in[6];
    const float* bp         = (const float*)d_in[7];
    const float* bias_table = (const float*)d_in[8];
    const int*   rel_idx    = (const int*)d_in[9];
    float* out = (float*)d_out;

    __half *xh = nullptr, *qkvh = nullptr, *oh = nullptr, *wh = nullptr, *wph = nullptr;
    cudaGetSymbolAddress((void**)&xh,   g_xh);
    cudaGetSymbolAddress((void**)&qkvh, g_qkvh);
    cudaGetSymbolAddress((void**)&oh,   g_oh);
    cudaGetSymbolAddress((void**)&wh,   g_wh);
    cudaGetSymbolAddress((void**)&wph,  g_wph);

    const int M = NWIN * NTOK;   // 524288

    // 0) fp32 -> fp16 conversions
    cvt_f32_f16<<<(M * DIM) / 2048, 256>>>(x, xh, M * DIM);
    cvt_f32_f16<<<(DIM * DIM) / 2048, 256>>>(wq, wh, DIM * DIM);
    cvt_f32_f16<<<(2 * DIM * DIM) / 2048, 256>>>(wkv, wh + DIM * DIM, 2 * DIM * DIM);
    cvt_f32_f16<<<(DIM * DIM) / 2048, 256>>>(wp, wph, DIM * DIM);

    // 1) QKV projection: qkv[M,768] = xh @ [wq;wkv]^T + [bq;bkv]  (f16 out)
    gemm_f16<true><<<dim3(QKVC / 128, M / 128), 256>>>(
        xh, wh, bq, bkv, DIM, qkvh, M, QKVC, DIM);

    // 2) windowed attention (f16 in, f16 out)
    attn_kernel<<<NWIN, 256>>>(qkvh, mask, bias_table, rel_idx, oh);

    // 3) output projection: out[M,256] = oh @ wp^T + bp  (f32 out)
    gemm_f16<false><<<dim3(DIM / 128, M / 128), 256>>>(
        oh, wph, bp, bp, DIM, out, M, DIM, DIM);
}